// round 2
// baseline (speedup 1.0000x reference)
#include <cuda_runtime.h>
#include <cstdint>

#define N_POINTS   262144
#define N_LEVELS   16
#define TABLE_SIZE 524288
#define HASH_MASK  0x7FFFFu
#define P2 2654435761u
#define P3 805459861u

__global__ __launch_bounds__(256, 8)
void hashgrid_encode_kernel(const float* __restrict__ xyz,
                            const float* __restrict__ tables,
                            const int*   __restrict__ resolutions,
                            float*       __restrict__ out)
{
    const int tid   = blockIdx.x * blockDim.x + threadIdx.x;
    const int level = tid & (N_LEVELS - 1);
    const int point = tid >> 4;
    if (point >= N_POINTS) return;

    // xyz load: all 16 lanes of a level-group read the same point -> L1 broadcast
    const float px = __ldg(xyz + 3 * point + 0);
    const float py = __ldg(xyz + 3 * point + 1);
    const float pz = __ldg(xyz + 3 * point + 2);

    const float resf = (float)__ldg(resolutions + level);

    // clip(xyz/SIZE + 0.5, 0, 1-1e-6), SIZE=1
    const float HI = (float)(1.0 - 1e-6);   // computed in double, matches JAX
    float ux = fminf(fmaxf(px + 0.5f, 0.0f), HI);
    float uy = fminf(fmaxf(py + 0.5f, 0.0f), HI);
    float uz = fminf(fmaxf(pz + 0.5f, 0.0f), HI);

    // grid coords
    float gx = ux * resf, gy = uy * resf, gz = uz * resf;
    float fx = floorf(gx), fy = floorf(gy), fz = floorf(gz);
    float wx1 = gx - fx, wy1 = gy - fy, wz1 = gz - fz;
    float wx0 = 1.0f - wx1, wy0 = 1.0f - wy1, wz0 = 1.0f - wz1;

    uint32_t ix = (uint32_t)fx, iy = (uint32_t)fy, iz = (uint32_t)fz;

    // incremental hash components (prime for x is 1)
    uint32_t hx0 = ix,        hx1 = ix + 1u;
    uint32_t hy0 = iy * P2,   hy1 = hy0 + P2;
    uint32_t hz0 = iz * P3,   hz1 = hz0 + P3;

    // corner c: dx=(c>>2)&1, dy=(c>>1)&1, dz=c&1
    uint32_t idx0 = (hx0 ^ hy0 ^ hz0) & HASH_MASK;
    uint32_t idx1 = (hx0 ^ hy0 ^ hz1) & HASH_MASK;
    uint32_t idx2 = (hx0 ^ hy1 ^ hz0) & HASH_MASK;
    uint32_t idx3 = (hx0 ^ hy1 ^ hz1) & HASH_MASK;
    uint32_t idx4 = (hx1 ^ hy0 ^ hz0) & HASH_MASK;
    uint32_t idx5 = (hx1 ^ hy0 ^ hz1) & HASH_MASK;
    uint32_t idx6 = (hx1 ^ hy1 ^ hz0) & HASH_MASK;
    uint32_t idx7 = (hx1 ^ hy1 ^ hz1) & HASH_MASK;

    const float2* __restrict__ tab =
        (const float2*)tables + (size_t)level * TABLE_SIZE;

    // issue all 8 gathers before consuming (MLP=8 hides L2 latency)
    float2 f0 = __ldg(tab + idx0);
    float2 f1 = __ldg(tab + idx1);
    float2 f2 = __ldg(tab + idx2);
    float2 f3 = __ldg(tab + idx3);
    float2 f4 = __ldg(tab + idx4);
    float2 f5 = __ldg(tab + idx5);
    float2 f6 = __ldg(tab + idx6);
    float2 f7 = __ldg(tab + idx7);

    float w0 = wx0 * wy0 * wz0;
    float w1 = wx0 * wy0 * wz1;
    float w2 = wx0 * wy1 * wz0;
    float w3 = wx0 * wy1 * wz1;
    float w4 = wx1 * wy0 * wz0;
    float w5 = wx1 * wy0 * wz1;
    float w6 = wx1 * wy1 * wz0;
    float w7 = wx1 * wy1 * wz1;

    float o0 = w0 * f0.x + w1 * f1.x + w2 * f2.x + w3 * f3.x
             + w4 * f4.x + w5 * f5.x + w6 * f6.x + w7 * f7.x;
    float o1 = w0 * f0.y + w1 * f1.y + w2 * f2.y + w3 * f3.y
             + w4 * f4.y + w5 * f5.y + w6 * f6.y + w7 * f7.y;

    // out[point, level*2 .. level*2+1]; lanes (l=0..15) of a point write one
    // contiguous 128B span -> fully coalesced float2 stores
    float2* __restrict__ outv = (float2*)out;
    outv[(size_t)point * N_LEVELS + level] = make_float2(o0, o1);
}

extern "C" void kernel_launch(void* const* d_in, const int* in_sizes, int n_in,
                              void* d_out, int out_size)
{
    const float* xyz         = (const float*)d_in[0];
    const float* tables      = (const float*)d_in[1];
    const int*   resolutions = (const int*)d_in[2];
    float*       out         = (float*)d_out;

    const int total   = N_POINTS * N_LEVELS;      // 4,194,304 threads
    const int threads = 256;
    const int blocks  = total / threads;          // 16384
    hashgrid_encode_kernel<<<blocks, threads>>>(xyz, tables, resolutions, out);
}